// round 2
// baseline (speedup 1.0000x reference)
#include <cuda_runtime.h>
#include <cstdint>

#define DIM 128
#define NMAX 100000

// Scratch (device globals: allocation-free per harness rules)
__device__ float g_agg[(size_t)NMAX * DIM];
__device__ int   g_deg_out[NMAX];
__device__ int   g_deg_in[NMAX];
__device__ float g_inv_out[NMAX];
__device__ float g_inv_in[NMAX];
__device__ float g_hsum[DIM];

// ---------------------------------------------------------------------------
// 1) degree counting (edges only; self-loop handled as +1 in norm kernel)
// ---------------------------------------------------------------------------
__global__ void deg_kernel(const int* __restrict__ src, const int* __restrict__ dst,
                           int n_edges) {
    int i = blockIdx.x * blockDim.x + threadIdx.x;
    int stride = gridDim.x * blockDim.x;
    for (; i < n_edges; i += stride) {
        atomicAdd(&g_deg_out[src[i]], 1);
        atomicAdd(&g_deg_in[dst[i]], 1);
    }
}

// ---------------------------------------------------------------------------
// 2) inverse-sqrt degree norms (self loop -> deg+1, always >= 1)
// ---------------------------------------------------------------------------
__global__ void norm_kernel(int n_nodes) {
    int i = blockIdx.x * blockDim.x + threadIdx.x;
    if (i < n_nodes) {
        g_inv_out[i] = rsqrtf((float)(g_deg_out[i] + 1));
        g_inv_in[i]  = rsqrtf((float)(g_deg_in[i] + 1));
    }
}

// ---------------------------------------------------------------------------
// 3) SpMM scatter: warp per edge, lane handles one float4 (128B/warp row slice)
//    agg[d] += h[s] * inv_out[s]    (vector float4 atomics, sm_90+)
// ---------------------------------------------------------------------------
__global__ void scatter_kernel(const float4* __restrict__ h4,
                               const int* __restrict__ src,
                               const int* __restrict__ dst,
                               int n_edges) {
    int lane = threadIdx.x & 31;
    int e = blockIdx.x * (blockDim.x >> 5) + (threadIdx.x >> 5);
    if (e >= n_edges) return;
    int s = __ldg(&src[e]);
    int d = __ldg(&dst[e]);
    float sc = g_inv_out[s];
    float4 v = __ldg(&h4[(size_t)s * 32 + lane]);
    float4 vv = make_float4(v.x * sc, v.y * sc, v.z * sc, v.w * sc);
    float4* p = (float4*)(g_agg + (size_t)d * DIM + lane * 4);
    atomicAdd(p, vv);
}

// ---------------------------------------------------------------------------
// 4) fused: x = (agg + h*inv_out)*inv_in ; y = relu(x @ W1 + b1) ;
//    accumulate sum over nodes into g_hsum (mean applied in head kernel).
//    Warp processes 4 nodes at a time; W1 resident in smem (64 KB);
//    packed f32x2 FMAs; lane owns outputs {2l,2l+1, 64+2l,64+2l+1}.
// ---------------------------------------------------------------------------
__global__ void gemv_mean_kernel(const float4* __restrict__ agg4,
                                 const float4* __restrict__ h4,
                                 const float* __restrict__ W1,
                                 const float* __restrict__ b1,
                                 int n_nodes) {
    extern __shared__ float W1s[];  // [128][128] fp32 = 64KB
    {
        float4* dsts = (float4*)W1s;
        const float4* srcs = (const float4*)W1;
        for (int i = threadIdx.x; i < DIM * DIM / 4; i += blockDim.x) dsts[i] = srcs[i];
    }
    __syncthreads();
    const unsigned long long* W1s2 = (const unsigned long long*)W1s;

    int lane  = threadIdx.x & 31;
    int warp  = blockIdx.x * (blockDim.x >> 5) + (threadIdx.x >> 5);
    int nwarp = gridDim.x * (blockDim.x >> 5);

    float2 bA = ((const float2*)b1)[lane];        // b1[2l], b1[2l+1]
    float2 bB = ((const float2*)b1)[lane + 32];   // b1[64+2l], b1[64+2l+1]

    float s0 = 0.f, s1 = 0.f, s2 = 0.f, s3 = 0.f;

    for (int base = warp * 4; base < n_nodes; base += nwarp * 4) {
        float4 xv[4];
        bool valid[4];
#pragma unroll
        for (int m = 0; m < 4; m++) {
            int n = base + m;
            valid[m] = (n < n_nodes);
            if (valid[m]) {
                float4 a  = agg4[(size_t)n * 32 + lane];
                float4 hh = h4[(size_t)n * 32 + lane];
                float wo = g_inv_out[n];
                float wi = g_inv_in[n];
                xv[m].x = (a.x + hh.x * wo) * wi;
                xv[m].y = (a.y + hh.y * wo) * wi;
                xv[m].z = (a.z + hh.z * wo) * wi;
                xv[m].w = (a.w + hh.w * wo) * wi;
            } else {
                xv[m] = make_float4(0.f, 0.f, 0.f, 0.f);
            }
        }

        unsigned long long accA[4] = {0ull, 0ull, 0ull, 0ull};
        unsigned long long accB[4] = {0ull, 0ull, 0ull, 0ull};

        for (int q = 0; q < 32; q++) {
#pragma unroll
            for (int c = 0; c < 4; c++) {
                int k = q * 4 + c;
                unsigned long long wA = W1s2[k * 64 + lane];       // W1[k][2l..2l+1]
                unsigned long long wB = W1s2[k * 64 + 32 + lane];  // W1[k][64+2l..64+2l+1]
#pragma unroll
                for (int m = 0; m < 4; m++) {
                    float xk = __shfl_sync(0xffffffffu,
                                           (c == 0) ? xv[m].x :
                                           (c == 1) ? xv[m].y :
                                           (c == 2) ? xv[m].z : xv[m].w, q);
                    unsigned xb = __float_as_uint(xk);
                    unsigned long long x2;
                    asm("mov.b64 %0, {%1, %2};" : "=l"(x2) : "r"(xb), "r"(xb));
                    asm("fma.rn.f32x2 %0, %1, %2, %0;" : "+l"(accA[m]) : "l"(wA), "l"(x2));
                    asm("fma.rn.f32x2 %0, %1, %2, %0;" : "+l"(accB[m]) : "l"(wB), "l"(x2));
                }
            }
        }

#pragma unroll
        for (int m = 0; m < 4; m++) {
            if (!valid[m]) continue;
            unsigned alo, ahi, blo, bhi;
            asm("mov.b64 {%0, %1}, %2;" : "=r"(alo), "=r"(ahi) : "l"(accA[m]));
            asm("mov.b64 {%0, %1}, %2;" : "=r"(blo), "=r"(bhi) : "l"(accB[m]));
            s0 += fmaxf(__uint_as_float(alo) + bA.x, 0.f);
            s1 += fmaxf(__uint_as_float(ahi) + bA.y, 0.f);
            s2 += fmaxf(__uint_as_float(blo) + bB.x, 0.f);
            s3 += fmaxf(__uint_as_float(bhi) + bB.y, 0.f);
        }
    }

    atomicAdd(&g_hsum[2 * lane],          s0);
    atomicAdd(&g_hsum[2 * lane + 1],      s1);
    atomicAdd(&g_hsum[64 + 2 * lane],     s2);
    atomicAdd(&g_hsum[64 + 2 * lane + 1], s3);
}

// ---------------------------------------------------------------------------
// 5) classifier heads: out[0:16] = hg@Wc1+bc1, out[16:32] = hg@Wc2+bc2
// ---------------------------------------------------------------------------
__global__ void head_kernel(const float* __restrict__ Wc1, const float* __restrict__ bc1,
                            const float* __restrict__ Wc2, const float* __restrict__ bc2,
                            float* __restrict__ out, float inv_n) {
    int t = threadIdx.x;
    if (t >= 32) return;
    const float* Wc = (t < 16) ? Wc1 : Wc2;
    const float* bc = (t < 16) ? bc1 : bc2;
    int c = t & 15;
    float acc = 0.f;
#pragma unroll 8
    for (int k = 0; k < DIM; k++) acc += g_hsum[k] * Wc[k * 16 + c];
    out[t] = acc * inv_n + bc[c];
}

// ---------------------------------------------------------------------------
extern "C" void kernel_launch(void* const* d_in, const int* in_sizes, int n_in,
                              void* d_out, int out_size) {
    const float* h   = (const float*)d_in[0];
    const int*   src = (const int*)d_in[1];
    const int*   dst = (const int*)d_in[2];
    const float* W1  = (const float*)d_in[3];
    const float* b1  = (const float*)d_in[4];
    const float* Wc1 = (const float*)d_in[5];
    const float* bc1 = (const float*)d_in[6];
    const float* Wc2 = (const float*)d_in[7];
    const float* bc2 = (const float*)d_in[8];

    int n_nodes = in_sizes[0] / DIM;
    int n_edges = in_sizes[1];

    // One-time attribute setup (outside the captured stream-op sequence).
    static bool s_init = false;
    if (!s_init) {
        cudaFuncSetAttribute(gemv_mean_kernel,
                             cudaFuncAttributeMaxDynamicSharedMemorySize, 65536);
        s_init = true;
    }

    void *agg_p = nullptr, *do_p = nullptr, *di_p = nullptr, *hs_p = nullptr;
    cudaGetSymbolAddress(&agg_p, g_agg);
    cudaGetSymbolAddress(&do_p, g_deg_out);
    cudaGetSymbolAddress(&di_p, g_deg_in);
    cudaGetSymbolAddress(&hs_p, g_hsum);

    cudaMemsetAsync(agg_p, 0, (size_t)n_nodes * DIM * sizeof(float));
    cudaMemsetAsync(do_p, 0, (size_t)n_nodes * sizeof(int));
    cudaMemsetAsync(di_p, 0, (size_t)n_nodes * sizeof(int));
    cudaMemsetAsync(hs_p, 0, DIM * sizeof(float));

    deg_kernel<<<(n_edges + 511) / 512, 512>>>(src, dst, n_edges);
    norm_kernel<<<(n_nodes + 255) / 256, 256>>>(n_nodes);

    // warp per edge: 8 warps / 256-thread block
    scatter_kernel<<<(n_edges + 7) / 8, 256>>>((const float4*)h, src, dst, n_edges);

    gemv_mean_kernel<<<444, 256, 65536>>>((const float4*)agg_p, (const float4*)h,
                                          W1, b1, n_nodes);

    head_kernel<<<1, 32>>>(Wc1, bc1, Wc2, bc2, (float*)d_out, 1.0f / (float)n_nodes);
}

// round 3
// speedup vs baseline: 1.6143x; 1.6143x over previous
#include <cuda_runtime.h>
#include <cstdint>

#define DIM 128
#define NMAX 100000
#define EMAX 1600000
#define SCAN_BLK 1024

// Scratch (device globals: allocation-free per harness rules)
__device__ float g_x[(size_t)NMAX * DIM];      // normalized conv input x
__device__ int   g_deg_out[NMAX];
__device__ int   g_deg_in[NMAX];
__device__ float g_inv_out[NMAX];
__device__ float g_inv_in[NMAX];
__device__ int   g_row_ptr[NMAX + 1];
__device__ int   g_cursor[NMAX];
__device__ int   g_csr_src[EMAX];
__device__ int   g_blksum[256];
__device__ int   g_blkoff[256];
__device__ int   g_scan_tmp[NMAX];
__device__ float g_hsum[DIM];

// ---------------------------------------------------------------------------
// 1) degree counting (edges only; self-loop handled as +1 in norm kernel)
// ---------------------------------------------------------------------------
__global__ void deg_kernel(const int* __restrict__ src, const int* __restrict__ dst,
                           int n_edges) {
    int i = blockIdx.x * blockDim.x + threadIdx.x;
    int stride = gridDim.x * blockDim.x;
    for (; i < n_edges; i += stride) {
        atomicAdd(&g_deg_out[src[i]], 1);
        atomicAdd(&g_deg_in[dst[i]], 1);
    }
}

// ---------------------------------------------------------------------------
// 2) inverse-sqrt degree norms (self loop -> deg+1, always >= 1)
// ---------------------------------------------------------------------------
__global__ void norm_kernel(int n_nodes) {
    int i = blockIdx.x * blockDim.x + threadIdx.x;
    if (i < n_nodes) {
        g_inv_out[i] = rsqrtf((float)(g_deg_out[i] + 1));
        g_inv_in[i]  = rsqrtf((float)(g_deg_in[i] + 1));
    }
}

// ---------------------------------------------------------------------------
// 3) exclusive scan of deg_in -> row_ptr  (3-kernel 2-level scan)
// ---------------------------------------------------------------------------
__global__ void scan1_kernel(int n) {
    __shared__ int sm[SCAN_BLK];
    int i = blockIdx.x * SCAN_BLK + threadIdx.x;
    int v = (i < n) ? g_deg_in[i] : 0;
    sm[threadIdx.x] = v;
    __syncthreads();
#pragma unroll
    for (int off = 1; off < SCAN_BLK; off <<= 1) {
        int t = (threadIdx.x >= off) ? sm[threadIdx.x - off] : 0;
        __syncthreads();
        sm[threadIdx.x] += t;
        __syncthreads();
    }
    if (i < n) g_scan_tmp[i] = sm[threadIdx.x] - v;   // exclusive
    if (threadIdx.x == SCAN_BLK - 1) g_blksum[blockIdx.x] = sm[SCAN_BLK - 1];
}

__global__ void scan2_kernel(int nb) {
    __shared__ int sm[256];
    int t = threadIdx.x;
    int v = (t < nb) ? g_blksum[t] : 0;
    sm[t] = v;
    __syncthreads();
#pragma unroll
    for (int off = 1; off < 256; off <<= 1) {
        int u = (t >= off) ? sm[t - off] : 0;
        __syncthreads();
        sm[t] += u;
        __syncthreads();
    }
    if (t < nb) g_blkoff[t] = sm[t] - v;   // exclusive
}

__global__ void scan3_kernel(int n, int n_edges) {
    int i = blockIdx.x * blockDim.x + threadIdx.x;
    if (i < n) {
        int r = g_scan_tmp[i] + g_blkoff[i / SCAN_BLK];
        g_row_ptr[i] = r;
        g_cursor[i] = r;
    }
    if (i == 0) g_row_ptr[n] = n_edges;
}

// ---------------------------------------------------------------------------
// 4) bucket fill: csr_src grouped by dst
// ---------------------------------------------------------------------------
__global__ void fill_kernel(const int* __restrict__ src, const int* __restrict__ dst,
                            int n_edges) {
    int i = blockIdx.x * blockDim.x + threadIdx.x;
    if (i >= n_edges) return;
    int d = dst[i];
    int pos = atomicAdd(&g_cursor[d], 1);
    g_csr_src[pos] = src[i];
}

// ---------------------------------------------------------------------------
// 5) aggregation: warp per dst row; x = (sum h[s]*wo[s] + h[d]*wo[d]) * wi[d]
//    No atomics; each x row written exactly once.
// ---------------------------------------------------------------------------
__global__ void agg_x_kernel(const float4* __restrict__ h4, int n_nodes) {
    int lane = threadIdx.x & 31;
    int d = blockIdx.x * (blockDim.x >> 5) + (threadIdx.x >> 5);
    if (d >= n_nodes) return;

    float wo = g_inv_out[d];
    float4 hv = __ldg(&h4[(size_t)d * 32 + lane]);
    float4 a0 = make_float4(hv.x * wo, hv.y * wo, hv.z * wo, hv.w * wo);
    float4 a1 = make_float4(0.f, 0.f, 0.f, 0.f);

    int beg = g_row_ptr[d], end = g_row_ptr[d + 1];
    int i = beg;
    for (; i + 2 <= end; i += 2) {
        int s0 = g_csr_src[i];
        int s1 = g_csr_src[i + 1];
        float c0 = g_inv_out[s0];
        float c1 = g_inv_out[s1];
        float4 v0 = __ldg(&h4[(size_t)s0 * 32 + lane]);
        float4 v1 = __ldg(&h4[(size_t)s1 * 32 + lane]);
        a0.x = fmaf(v0.x, c0, a0.x); a0.y = fmaf(v0.y, c0, a0.y);
        a0.z = fmaf(v0.z, c0, a0.z); a0.w = fmaf(v0.w, c0, a0.w);
        a1.x = fmaf(v1.x, c1, a1.x); a1.y = fmaf(v1.y, c1, a1.y);
        a1.z = fmaf(v1.z, c1, a1.z); a1.w = fmaf(v1.w, c1, a1.w);
    }
    if (i < end) {
        int s0 = g_csr_src[i];
        float c0 = g_inv_out[s0];
        float4 v0 = __ldg(&h4[(size_t)s0 * 32 + lane]);
        a0.x = fmaf(v0.x, c0, a0.x); a0.y = fmaf(v0.y, c0, a0.y);
        a0.z = fmaf(v0.z, c0, a0.z); a0.w = fmaf(v0.w, c0, a0.w);
    }

    float wi = g_inv_in[d];
    float4 out;
    out.x = (a0.x + a1.x) * wi;
    out.y = (a0.y + a1.y) * wi;
    out.z = (a0.z + a1.z) * wi;
    out.w = (a0.w + a1.w) * wi;
    ((float4*)g_x)[(size_t)d * 32 + lane] = out;
}

// ---------------------------------------------------------------------------
// 6) fused GEMV + relu + mean-sum.  K-paired f32x2 accumulators:
//    acc[m][c] = (sum_{k even-of-pair} W[k][j] x[k], sum_{k odd}) ; y = lo+hi.
//    Weights staged in smem as Wp[t2][j] = float4(W[4t2..4t2+3][j]) ->
//    coalesced LDS.128; x staged per-warp in smem, read as broadcasts.
//    Lane owns outputs j = {lane, 32+lane, 64+lane, 96+lane}.
// ---------------------------------------------------------------------------
#define GW 8   // warps per block
__global__ __launch_bounds__(256, 2)
void gemv2_kernel(const float4* __restrict__ x4, const float* __restrict__ W1,
                  const float* __restrict__ b1, int n_nodes) {
    extern __shared__ float4 dyn[];
    float4* Wp   = dyn;          // [32][128] float4 = 64KB
    float4* xbuf = dyn + 4096;   // [GW][4][32] float4 = 16KB

    for (int idx = threadIdx.x; idx < 4096; idx += blockDim.x) {
        int t2 = idx >> 7, j = idx & 127;
        Wp[t2 * 128 + j] = make_float4(W1[(4 * t2 + 0) * 128 + j],
                                       W1[(4 * t2 + 1) * 128 + j],
                                       W1[(4 * t2 + 2) * 128 + j],
                                       W1[(4 * t2 + 3) * 128 + j]);
    }
    __syncthreads();

    int lane = threadIdx.x & 31;
    int wi   = threadIdx.x >> 5;
    int warp = blockIdx.x * GW + wi;
    int nwarp = gridDim.x * GW;

    float bb[4], s[4];
#pragma unroll
    for (int c = 0; c < 4; c++) {
        bb[c] = b1[c * 32 + lane];
        s[c] = 0.f;
    }

    const ulonglong2* Wp2 = (const ulonglong2*)Wp;
    const ulonglong2* xb  = (const ulonglong2*)&xbuf[wi * 4 * 32];

    for (int base = warp * 4; base < n_nodes; base += nwarp * 4) {
        __syncwarp();
#pragma unroll
        for (int m = 0; m < 4; m++) {
            int n = base + m;
            xbuf[(wi * 4 + m) * 32 + lane] =
                (n < n_nodes) ? __ldg(&x4[(size_t)n * 32 + lane])
                              : make_float4(0.f, 0.f, 0.f, 0.f);
        }
        __syncwarp();

        unsigned long long acc[4][4];
#pragma unroll
        for (int m = 0; m < 4; m++)
#pragma unroll
            for (int c = 0; c < 4; c++) acc[m][c] = 0ull;

#pragma unroll 4
        for (int t2 = 0; t2 < 32; t2++) {
            ulonglong2 wv[4];
#pragma unroll
            for (int c = 0; c < 4; c++)
                wv[c] = Wp2[t2 * 128 + c * 32 + lane];
#pragma unroll
            for (int m = 0; m < 4; m++) {
                ulonglong2 xm = xb[m * 32 + t2];   // broadcast
#pragma unroll
                for (int c = 0; c < 4; c++) {
                    asm("fma.rn.f32x2 %0, %1, %2, %0;"
                        : "+l"(acc[m][c]) : "l"(wv[c].x), "l"(xm.x));
                    asm("fma.rn.f32x2 %0, %1, %2, %0;"
                        : "+l"(acc[m][c]) : "l"(wv[c].y), "l"(xm.y));
                }
            }
        }

#pragma unroll
        for (int m = 0; m < 4; m++) {
            if (base + m >= n_nodes) break;
#pragma unroll
            for (int c = 0; c < 4; c++) {
                unsigned lo, hi;
                asm("mov.b64 {%0, %1}, %2;" : "=r"(lo), "=r"(hi) : "l"(acc[m][c]));
                float y = __uint_as_float(lo) + __uint_as_float(hi) + bb[c];
                s[c] += fmaxf(y, 0.f);
            }
        }
    }

#pragma unroll
    for (int c = 0; c < 4; c++)
        atomicAdd(&g_hsum[c * 32 + lane], s[c]);
}

// ---------------------------------------------------------------------------
// 7) classifier heads: out[0:16] = hg@Wc1+bc1, out[16:32] = hg@Wc2+bc2
// ---------------------------------------------------------------------------
__global__ void head_kernel(const float* __restrict__ Wc1, const float* __restrict__ bc1,
                            const float* __restrict__ Wc2, const float* __restrict__ bc2,
                            float* __restrict__ out, float inv_n) {
    int t = threadIdx.x;
    if (t >= 32) return;
    const float* Wc = (t < 16) ? Wc1 : Wc2;
    const float* bc = (t < 16) ? bc1 : bc2;
    int c = t & 15;
    float acc = 0.f;
#pragma unroll 8
    for (int k = 0; k < DIM; k++) acc += g_hsum[k] * Wc[k * 16 + c];
    out[t] = acc * inv_n + bc[c];
}

// ---------------------------------------------------------------------------
extern "C" void kernel_launch(void* const* d_in, const int* in_sizes, int n_in,
                              void* d_out, int out_size) {
    const float* h   = (const float*)d_in[0];
    const int*   src = (const int*)d_in[1];
    const int*   dst = (const int*)d_in[2];
    const float* W1  = (const float*)d_in[3];
    const float* b1  = (const float*)d_in[4];
    const float* Wc1 = (const float*)d_in[5];
    const float* bc1 = (const float*)d_in[6];
    const float* Wc2 = (const float*)d_in[7];
    const float* bc2 = (const float*)d_in[8];

    int n_nodes = in_sizes[0] / DIM;
    int n_edges = in_sizes[1];

    static bool s_init = false;
    if (!s_init) {
        cudaFuncSetAttribute(gemv2_kernel,
                             cudaFuncAttributeMaxDynamicSharedMemorySize, 81920);
        s_init = true;
    }

    void *do_p = nullptr, *di_p = nullptr, *hs_p = nullptr, *x_p = nullptr;
    cudaGetSymbolAddress(&do_p, g_deg_out);
    cudaGetSymbolAddress(&di_p, g_deg_in);
    cudaGetSymbolAddress(&hs_p, g_hsum);
    cudaGetSymbolAddress(&x_p, g_x);

    cudaMemsetAsync(do_p, 0, (size_t)n_nodes * sizeof(int));
    cudaMemsetAsync(di_p, 0, (size_t)n_nodes * sizeof(int));
    cudaMemsetAsync(hs_p, 0, DIM * sizeof(float));

    deg_kernel<<<(n_edges + 511) / 512, 512>>>(src, dst, n_edges);
    norm_kernel<<<(n_nodes + 255) / 256, 256>>>(n_nodes);

    int nb = (n_nodes + SCAN_BLK - 1) / SCAN_BLK;
    scan1_kernel<<<nb, SCAN_BLK>>>(n_nodes);
    scan2_kernel<<<1, 256>>>(nb);
    scan3_kernel<<<(n_nodes + 255) / 256, 256>>>(n_nodes, n_edges);

    fill_kernel<<<(n_edges + 255) / 256, 256>>>(src, dst, n_edges);

    agg_x_kernel<<<(n_nodes + 7) / 8, 256>>>((const float4*)h, n_nodes);

    gemv2_kernel<<<296, 256, 81920>>>((const float4*)x_p, W1, b1, n_nodes);

    head_kernel<<<1, 32>>>(Wc1, bc1, Wc2, bc2, (float*)d_out, 1.0f / (float)n_nodes);
}